// round 7
// baseline (speedup 1.0000x reference)
#include <cuda_runtime.h>
#include <cstdint>

// VectorQuantizer via 3xTF32 warp-level mma.sync (m16n8k8) + exact cleanup.
// inputs [131072, 64] f32, embeddings [512, 64] f32
// out (f32 buffer) = codes-as-float [131072] ++ code_vecs [131072*64]
//
// Fast path: dot = t0u0 + t0u1 + t1u0 (tf32 splits). Rows whose top-2
// distance margin < 1e-4 (>=10x the tensor-path error bound) are flagged
// and re-decided by vq_cleanup using the R3-validated exact fp32 arithmetic
// (interleaved lo/hi fma chains, lowest-index tie-break).

__device__ float vq_e2[512];
// B fragments: [split 2][nchunk 8][ntile 8][kpair 4][lane 32][comp 4] f32
__device__ __align__(16) float vq_bfrag[2 * 8 * 8 * 4 * 32 * 4];
__device__ int vq_nflag;
#define FLAG_CAP 32768
__device__ int vq_flags[FLAG_CAP];
#define THRESH 1e-4f

__device__ __forceinline__ uint32_t f2tf32(float x) {
    uint32_t r;
    asm("cvt.rna.tf32.f32 %0, %1;" : "=r"(r) : "f"(x));
    return r;
}

__device__ __forceinline__ void mma8(float* d, const uint32_t* a,
                                     uint32_t b0, uint32_t b1) {
    asm volatile(
        "mma.sync.aligned.m16n8k8.row.col.f32.tf32.tf32.f32 "
        "{%0,%1,%2,%3}, {%4,%5,%6,%7}, {%8,%9}, {%0,%1,%2,%3};"
        : "+f"(d[0]), "+f"(d[1]), "+f"(d[2]), "+f"(d[3])
        : "r"(a[0]), "r"(a[1]), "r"(a[2]), "r"(a[3]), "r"(b0), "r"(b1));
}

// ---------------- prep: B fragments + e2 + flag reset ----------------
__global__ void vq_prep(const float* __restrict__ emb) {
    int blk = blockIdx.x, tid = threadIdx.x;
    if (blk < 128) {
        int id = blk * 256 + tid;          // 0..32767
        int n = id >> 6, k = id & 63;
        float v = emb[n * 64 + k];
        uint32_t t0 = f2tf32(v);
        float rres = v - __uint_as_float(t0);
        uint32_t t1 = f2tf32(rres);
        int nc = n >> 6, nl = n & 63, nt = nl >> 3, g = nl & 7;
        int p = k >> 4, j = k & 3;
        int c = ((k >> 3) & 1) * 2 + ((k >> 2) & 1);
        int lane = g * 4 + j;
        int base = (((nc * 8 + nt) * 4 + p) * 32 + lane) * 4 + c;
        ((uint32_t*)vq_bfrag)[base]         = t0;   // split 0
        ((uint32_t*)vq_bfrag)[base + 32768] = t1;   // split 1
    } else {
        if (blk == 128 && tid == 0) vq_nflag = 0;   // reset every launch
        int code = (blk - 128) * 256 + tid;          // 0..511
        const float4* ep = (const float4*)(emb + code * 64);
        float s = 0.0f;
        #pragma unroll
        for (int q = 0; q < 16; ++q) {
            float4 v = ep[q];
            s += v.x * v.x + v.y * v.y + v.z * v.z + v.w * v.w;
        }
        vq_e2[code] = s;
    }
}

// ---------------- main (tensor path) ----------------
#define AR 68   // A_raw row stride in floats (17 float4s: conflict-free)

__global__ __launch_bounds__(256)
void vq_main(const float4* __restrict__ in4,    // [nrows][16]
             const float4* __restrict__ emb4,   // [512][16]
             float* __restrict__ codes_out,     // [nrows] (as float)
             float4* __restrict__ vecs_out)     // [nrows][16]
{
    __shared__ float A_raw[128 * AR];
    __shared__ float e2s[512];
    __shared__ float l2xs[128];
    __shared__ int   rc[128];

    const int tid  = threadIdx.x;
    const int w    = tid >> 5;
    const int lane = tid & 31;
    const int g    = lane >> 2;
    const int j    = lane & 3;
    const int row0 = blockIdx.x * 128;

    #pragma unroll
    for (int i = 0; i < 8; ++i) {
        int item = i * 256 + tid;
        int r = item >> 4, seg = item & 15;
        *(float4*)&A_raw[r * AR + seg * 4] = in4[(size_t)(row0 + r) * 16 + seg];
    }
    #pragma unroll
    for (int i = 0; i < 2; ++i) e2s[tid + i * 256] = vq_e2[tid + i * 256];
    __syncthreads();

    if (tid < 128) {
        float s = 0.0f;
        #pragma unroll
        for (int q = 0; q < 16; ++q) {
            float4 v = *(const float4*)&A_raw[tid * AR + q * 4];
            s += v.x * v.x + v.y * v.y + v.z * v.z + v.w * v.w;
        }
        l2xs[tid] = s;
    }

    uint32_t a[2][8][4];
    {
        const int rlo = (w * 16 + g) * AR;
        const int rhi = (w * 16 + g + 8) * AR;
        #pragma unroll
        for (int kst = 0; kst < 8; ++kst) {
            float x0 = A_raw[rlo + kst * 8 + j];
            float x1 = A_raw[rhi + kst * 8 + j];
            float x2 = A_raw[rlo + kst * 8 + j + 4];
            float x3 = A_raw[rhi + kst * 8 + j + 4];
            a[0][kst][0] = f2tf32(x0);
            a[0][kst][1] = f2tf32(x1);
            a[0][kst][2] = f2tf32(x2);
            a[0][kst][3] = f2tf32(x3);
            a[1][kst][0] = f2tf32(x0 - __uint_as_float(a[0][kst][0]));
            a[1][kst][1] = f2tf32(x1 - __uint_as_float(a[0][kst][1]));
            a[1][kst][2] = f2tf32(x2 - __uint_as_float(a[0][kst][2]));
            a[1][kst][3] = f2tf32(x3 - __uint_as_float(a[0][kst][3]));
        }
    }
    __syncthreads();

    const float l2lo = l2xs[w * 16 + g];
    const float l2hi = l2xs[w * 16 + g + 8];
    float bdlo = 3.4e38f, bdhi = 3.4e38f;     // best
    float b2lo = 3.4e38f, b2hi = 3.4e38f;     // second best (value only)
    int   bilo = 0,       bihi = 0;

    const float4* bf4 = (const float4*)vq_bfrag;

    for (int nc = 0; nc < 8; ++nc) {
        float d[8][4];
        #pragma unroll
        for (int t = 0; t < 8; ++t)
            #pragma unroll
            for (int c = 0; c < 4; ++c) d[t][c] = 0.0f;

        const float4* b0c = bf4 + ((size_t)nc * 8) * 4 * 32;
        const float4* b1c = b0c + 8192;

        #pragma unroll
        for (int p = 0; p < 4; ++p) {
            #pragma unroll
            for (int ntg = 0; ntg < 2; ++ntg) {
                float4 B0[4], B1[4];
                #pragma unroll
                for (int q = 0; q < 4; ++q) {
                    int nt = ntg * 4 + q;
                    B0[q] = b0c[(nt * 4 + p) * 32 + lane];
                    B1[q] = b1c[(nt * 4 + p) * 32 + lane];
                }
                #pragma unroll
                for (int q = 0; q < 4; ++q)
                    mma8(d[ntg*4+q], a[0][2*p],   __float_as_uint(B0[q].x), __float_as_uint(B0[q].y));
                #pragma unroll
                for (int q = 0; q < 4; ++q)
                    mma8(d[ntg*4+q], a[0][2*p+1], __float_as_uint(B0[q].z), __float_as_uint(B0[q].w));
                #pragma unroll
                for (int q = 0; q < 4; ++q)
                    mma8(d[ntg*4+q], a[0][2*p],   __float_as_uint(B1[q].x), __float_as_uint(B1[q].y));
                #pragma unroll
                for (int q = 0; q < 4; ++q)
                    mma8(d[ntg*4+q], a[0][2*p+1], __float_as_uint(B1[q].z), __float_as_uint(B1[q].w));
                #pragma unroll
                for (int q = 0; q < 4; ++q)
                    mma8(d[ntg*4+q], a[1][2*p],   __float_as_uint(B0[q].x), __float_as_uint(B0[q].y));
                #pragma unroll
                for (int q = 0; q < 4; ++q)
                    mma8(d[ntg*4+q], a[1][2*p+1], __float_as_uint(B0[q].z), __float_as_uint(B0[q].w));
            }
        }

        #pragma unroll
        for (int nt = 0; nt < 8; ++nt) {
            int n0 = nc * 64 + nt * 8 + j * 2;
            float e0 = e2s[n0], e1 = e2s[n0 + 1];
            float t, dist;
            t = l2lo + e0; dist = fmaf(-2.0f, d[nt][0], t);
            if (dist < bdlo) { b2lo = bdlo; bdlo = dist; bilo = n0; }
            else if (dist < b2lo) b2lo = dist;
            t = l2lo + e1; dist = fmaf(-2.0f, d[nt][1], t);
            if (dist < bdlo) { b2lo = bdlo; bdlo = dist; bilo = n0 + 1; }
            else if (dist < b2lo) b2lo = dist;
            t = l2hi + e0; dist = fmaf(-2.0f, d[nt][2], t);
            if (dist < bdhi) { b2hi = bdhi; bdhi = dist; bihi = n0; }
            else if (dist < b2hi) b2hi = dist;
            t = l2hi + e1; dist = fmaf(-2.0f, d[nt][3], t);
            if (dist < bdhi) { b2hi = bdhi; bdhi = dist; bihi = n0 + 1; }
            else if (dist < b2hi) b2hi = dist;
        }
    }

    // ---- reduce across the 4 j-lanes: (best,index) + second-best value ----
    #pragma unroll
    for (int off = 1; off <= 2; off <<= 1) {
        float o1, o2; int oi;
        o1 = __shfl_xor_sync(0xFFFFFFFFu, bdlo, off);
        oi = __shfl_xor_sync(0xFFFFFFFFu, bilo, off);
        o2 = __shfl_xor_sync(0xFFFFFFFFu, b2lo, off);
        b2lo = fminf(fminf(b2lo, o2), fmaxf(bdlo, o1));
        if (o1 < bdlo || (o1 == bdlo && oi < bilo)) { bdlo = o1; bilo = oi; }
        o1 = __shfl_xor_sync(0xFFFFFFFFu, bdhi, off);
        oi = __shfl_xor_sync(0xFFFFFFFFu, bihi, off);
        o2 = __shfl_xor_sync(0xFFFFFFFFu, b2hi, off);
        b2hi = fminf(fminf(b2hi, o2), fmaxf(bdhi, o1));
        if (o1 < bdhi || (o1 == bdhi && oi < bihi)) { bdhi = o1; bihi = oi; }
    }
    if (j == 0) {
        int rlo = w * 16 + g, rhi = rlo + 8;
        rc[rlo] = bilo;  codes_out[row0 + rlo] = (float)bilo;
        rc[rhi] = bihi;  codes_out[row0 + rhi] = (float)bihi;
        if (b2lo - bdlo < THRESH) {
            int s = atomicAdd(&vq_nflag, 1);
            if (s < FLAG_CAP) vq_flags[s] = row0 + rlo;
        }
        if (b2hi - bdhi < THRESH) {
            int s = atomicAdd(&vq_nflag, 1);
            if (s < FLAG_CAP) vq_flags[s] = row0 + rhi;
        }
    }
    __syncthreads();

    #pragma unroll
    for (int i = 0; i < 8; ++i) {
        int item = i * 256 + tid;
        int r = item >> 4, seg = item & 15;
        vecs_out[(size_t)(row0 + r) * 16 + seg] = emb4[rc[r] * 16 + seg];
    }
}

// ---------------- cleanup: exact R3 arithmetic on flagged rows ----------------
__global__ __launch_bounds__(256)
void vq_cleanup(const float* __restrict__ in,
                const float* __restrict__ emb,
                float* __restrict__ codes_out,
                float4* __restrict__ vecs_out)
{
    __shared__ float xs[64];
    __shared__ float l2x_sh;
    __shared__ float rv[256];
    __shared__ int   ri[256];

    const int tid = threadIdx.x;
    int n = vq_nflag;
    if (n > FLAG_CAP) n = FLAG_CAP;

    for (int f = blockIdx.x; f < n; f += gridDim.x) {
        const int row = vq_flags[f];
        if (tid < 16)
            *(float4*)&xs[tid * 4] = ((const float4*)(in + (size_t)row * 64))[tid];
        __syncthreads();

        if (tid == 0) {
            float s = 0.0f;
            #pragma unroll
            for (int q = 0; q < 16; ++q) {
                float4 v = *(const float4*)&xs[q * 4];
                s += v.x * v.x + v.y * v.y + v.z * v.z + v.w * v.w;
            }
            l2x_sh = s;
        }
        __syncthreads();
        const float l2x = l2x_sh;

        float bv = 3.4e38f; int bi = 0;
        #pragma unroll
        for (int cc = 0; cc < 2; ++cc) {
            int c = tid + cc * 256;            // ascending per thread
            const float* e = emb + c * 64;
            // replicate R3's f32x2 interleaved accumulation exactly
            float lo = 0.0f, hi = 0.0f;
            #pragma unroll
            for (int dsg = 0; dsg < 16; ++dsg) {
                lo = fmaf(xs[4 * dsg],     e[4 * dsg],     lo);
                hi = fmaf(xs[4 * dsg + 1], e[4 * dsg + 1], hi);
                lo = fmaf(xs[4 * dsg + 2], e[4 * dsg + 2], lo);
                hi = fmaf(xs[4 * dsg + 3], e[4 * dsg + 3], hi);
            }
            float s2 = lo + hi;
            float t  = l2x + vq_e2[c];
            float dist = t - 2.0f * s2;        // single rounding (2*s2 exact)
            if (dist < bv) { bv = dist; bi = c; }
        }
        rv[tid] = bv; ri[tid] = bi;
        __syncthreads();
        #pragma unroll
        for (int st = 128; st > 0; st >>= 1) {
            if (tid < st) {
                float ov = rv[tid + st]; int oi = ri[tid + st];
                if (ov < rv[tid] || (ov == rv[tid] && oi < ri[tid])) {
                    rv[tid] = ov; ri[tid] = oi;
                }
            }
            __syncthreads();
        }
        const int best = ri[0];
        if (tid == 0) codes_out[row] = (float)best;
        if (tid < 16)
            vecs_out[(size_t)row * 16 + tid] =
                ((const float4*)(emb + best * 64))[tid];
        __syncthreads();
    }
}

extern "C" void kernel_launch(void* const* d_in, const int* in_sizes, int n_in,
                              void* d_out, int out_size)
{
    const int nrows  = in_sizes[0] / 64;     // 131072
    const int ntiles = nrows / 128;          // 1024

    float*  codes = (float*)d_out;
    float4* vecs  = (float4*)((float*)d_out + nrows);

    vq_prep<<<130, 256>>>((const float*)d_in[1]);
    vq_main<<<ntiles, 256>>>(
        (const float4*)d_in[0],
        (const float4*)d_in[1],
        codes, vecs);
    vq_cleanup<<<1024, 256>>>(
        (const float*)d_in[0],
        (const float*)d_in[1],
        codes, vecs);
}